// round 1
// baseline (speedup 1.0000x reference)
#include <cuda_runtime.h>
#include <math.h>

// Problem constants
#define GS   160          // spatial grid size (both ifft axes)
#define KD   128          // ks(16) * d(8) planes per tensor
#define NKS  16

// Scratch (static __device__ arrays per the allocation rules)
// g_tmp  : after pass-1 (transform along w):  [tensor][kd][w_k][h]
// g_field: after pass-2 (transform along h):  [tensor][h_k][w_k][kd]  (kd-contiguous 1KB cell)
__device__ float2 g_tmp[3][KD][GS][GS];
__device__ float2 g_field[3][GS][GS][KD];

struct Tw {
    float2 stw[5];   // radix-2 DIF stage twiddles exp(+2pi i j/(2H)), j=lane&(H-1)
    float2 ta[5];    // exp(+2pi i n2*k1/160)
    float2 t5[5];    // exp(+2pi i m/5)
    int    k1;       // brev5(lane)
};

__device__ __forceinline__ float2 cmulf(float2 a, float2 b){
    return make_float2(a.x*b.x - a.y*b.y, a.x*b.y + a.y*b.x);
}

__device__ __forceinline__ void make_tw(Tw &tw, int lane){
#pragma unroll
    for (int s = 0; s < 5; s++){
        int H = 16 >> s;
        int j = lane & (H - 1);
        float sv, cv;
        sincospif((float)j / (float)H, &sv, &cv);   // angle = pi*j/H = 2pi*j/(2H)
        tw.stw[s] = make_float2(cv, sv);
    }
    int k1 = (int)(__brev((unsigned)lane) >> 27);
    tw.k1 = k1;
#pragma unroll
    for (int n2 = 0; n2 < 5; n2++){
        float sv, cv;
        sincospif((float)(n2 * k1) / 80.0f, &sv, &cv);  // 2pi*n2*k1/160 = pi*(n2*k1/80)
        tw.ta[n2] = make_float2(cv, sv);
    }
#pragma unroll
    for (int m = 0; m < 5; m++){
        float sv, cv;
        sincospif(0.4f * (float)m, &sv, &cv);           // 2pi*m/5
        tw.t5[m] = make_float2(cv, sv);
    }
}

// Unnormalized inverse-sign DFT-160 across a warp.
// Input : lane L, v[j] = x[5*L + j], j=0..4
// Output: o[k2]  = X[k1 + 32*k2],  k1 = brev5(L),  X[k] = sum_n x[n] e^{+2pi i nk/160}
__device__ __forceinline__ void fft160(float2 v[5], float2 o[5], const Tw &tw, int lane){
#pragma unroll
    for (int s = 0; s < 5; s++){
        int H = 16 >> s;
        float2 t = tw.stw[s];
        bool up = (lane & H) != 0;
#pragma unroll
        for (int j = 0; j < 5; j++){
            float pr = __shfl_xor_sync(0xffffffffu, v[j].x, H);
            float pi = __shfl_xor_sync(0xffffffffu, v[j].y, H);
            float lr = v[j].x + pr;
            float li = v[j].y + pi;
            float dr = pr - v[j].x;          // partner - mine (upper lane holds x[j+H])
            float di = pi - v[j].y;
            float ur = dr * t.x - di * t.y;
            float ui = dr * t.y + di * t.x;
            v[j].x = up ? ur : lr;
            v[j].y = up ? ui : li;
        }
    }
    // lane-local combine over n2 (length-5 DFT with twiddle folded in)
    float2 B[5];
#pragma unroll
    for (int n2 = 0; n2 < 5; n2++) B[n2] = cmulf(v[n2], tw.ta[n2]);
#pragma unroll
    for (int k2 = 0; k2 < 5; k2++){
        float2 acc = B[0];
#pragma unroll
        for (int n2 = 1; n2 < 5; n2++){
            float2 w = tw.t5[(n2 * k2) % 5];
            acc.x += B[n2].x * w.x - B[n2].y * w.y;
            acc.y += B[n2].x * w.y + B[n2].y * w.x;
        }
        o[k2] = acc;
    }
}

// Pass 1: IDFT along w-axis. grid = (40, 128, 3), block = 128 (4 warps = 4 rows h)
__global__ void pass1_kernel(const float* __restrict__ pur, const float* __restrict__ pui,
                             const float* __restrict__ pvr, const float* __restrict__ pvi,
                             const float* __restrict__ pwr, const float* __restrict__ pwi,
                             const float* __restrict__ alpha_params)
{
    int t    = blockIdx.z;
    int kd   = blockIdx.y;
    int hb   = blockIdx.x;
    int wid  = threadIdx.x >> 5;
    int lane = threadIdx.x & 31;
    int h    = hb * 4 + wid;

    float a  = alpha_params[0];
    float bx = 10.0f * a;
    float alpha = (bx > 1.0f) ? a : (log1pf(expf(fminf(bx, 1.0f))) * 0.1f);
    float scale = alpha * (1.0f / 25600.0f);   // fold ifft2 normalization + alpha

    const float* re = (t == 0) ? pur : ((t == 1) ? pvr : pwr);
    const float* im = (t == 0) ? pui : ((t == 1) ? pvi : pwi);

    int k = kd >> 3, d = kd & 7;

    Tw tw; make_tw(tw, lane);
    float2 v[5], o[5];
#pragma unroll
    for (int j = 0; j < 5; j++){
        int w = 5 * lane + j;
        int idx;
        if      (t == 0) idx = (kd * GS + h) * GS + w;            // Pu: (k,d,y=h,z=w)
        else if (t == 1) idx = ((k * GS + h) * 8 + d) * GS + w;   // Pv: (k,X=h,d,Z=w)
        else             idx = ((k * GS + w) * GS + h) * 8 + d;   // Pw: (k,X=w,Y=h,d)
        v[j] = make_float2(re[idx] * scale, im[idx] * scale);
    }
    fft160(v, o, tw, lane);

    __shared__ float2 sm[GS][5];   // [w_k][warp], padded to 5 to break conflicts
#pragma unroll
    for (int k2 = 0; k2 < 5; k2++) sm[tw.k1 + 32 * k2][wid] = o[k2];
    __syncthreads();

    float2* dst = &g_tmp[t][kd][0][0];
    for (int idx = threadIdx.x; idx < GS * 4; idx += blockDim.x){
        int w = idx >> 2, j = idx & 3;
        dst[w * GS + hb * 4 + j] = sm[w][j];
    }
}

// Pass 2: IDFT along h-axis. grid = (160, 32, 3), block = 128 (4 warps = 4 kd)
__global__ void pass2_kernel()
{
    int t    = blockIdx.z;
    int kb   = blockIdx.y;
    int wk   = blockIdx.x;
    int wid  = threadIdx.x >> 5;
    int lane = threadIdx.x & 31;
    int kd   = kb * 4 + wid;

    Tw tw; make_tw(tw, lane);
    float2 v[5], o[5];
    const float2* src = &g_tmp[t][kd][wk][0];
#pragma unroll
    for (int j = 0; j < 5; j++) v[j] = src[5 * lane + j];
    fft160(v, o, tw, lane);

    __shared__ float2 sm[GS][5];   // [h_k][warp]
#pragma unroll
    for (int k2 = 0; k2 < 5; k2++) sm[tw.k1 + 32 * k2][wid] = o[k2];
    __syncthreads();

    for (int idx = threadIdx.x; idx < GS * 4; idx += blockDim.x){
        int h = idx >> 2, j = idx & 3;
        g_field[t][h][wk][kb * 4 + j] = sm[h][j];
    }
}

__device__ __forceinline__ float4 blend4(float4 a, float4 b, float4 c, float4 d,
                                         float w0, float w1, float w2, float w3){
    float4 r;
    r.x = w0*a.x + w1*b.x + w2*c.x + w3*d.x;
    r.y = w0*a.y + w1*b.y + w2*c.y + w3*d.y;
    r.z = w0*a.z + w1*b.z + w2*c.z + w3*d.z;
    r.w = w0*a.w + w1*b.w + w2*c.w + w3*d.w;
    return r;
}

// One warp per point. Lane L owns kd = 4L..4L+3 (one k, four d's).
__global__ void sample_kernel(const float* __restrict__ xyz,
                              const float* __restrict__ boundp,
                              float* __restrict__ out, int npts)
{
    int gw   = (int)((blockIdx.x * (unsigned)blockDim.x + threadIdx.x) >> 5);
    int lane = threadIdx.x & 31;
    if (gw >= npts) return;

    float invb = 1.0f / boundp[0];
    float px = xyz[3*gw + 0] * invb;
    float py = xyz[3*gw + 1] * invb;
    float pz = xyz[3*gw + 2] * invb;

    bool hi = (lane & 1) != 0;          // lane parity selects d range 0-3 vs 4-7
    float gacc = 0.0f;

#pragma unroll
    for (int t = 0; t < 3; t++){
        float gx = (t == 2) ? px : pz;          // W coordinate
        float gy = (t == 1) ? px : py;          // H coordinate
        float mc = (t == 0) ? px : ((t == 1) ? py : pz);  // modulation coordinate

        float ix = (gx + 1.0f) * 0.5f * 159.0f;
        float iy = (gy + 1.0f) * 0.5f * 159.0f;
        float fx = floorf(ix), fy = floorf(iy);
        float wx = ix - fx,    wy = iy - fy;
        int i0 = (int)fx, j0 = (int)fy;
        int i1 = i0 + 1,  j1 = j0 + 1;

        float vx0 = (i0 >= 0 && i0 <= 159) ? 1.0f : 0.0f;
        float vx1 = (i1 >= 0 && i1 <= 159) ? 1.0f : 0.0f;
        float vy0 = (j0 >= 0 && j0 <= 159) ? 1.0f : 0.0f;
        float vy1 = (j1 >= 0 && j1 <= 159) ? 1.0f : 0.0f;
        int i0c = max(0, min(159, i0)), i1c = max(0, min(159, i1));
        int j0c = max(0, min(159, j0)), j1c = max(0, min(159, j1));

        float w00 = (1.0f - wx) * (1.0f - wy) * vx0 * vy0;
        float w01 = wx          * (1.0f - wy) * vx1 * vy0;
        float w10 = (1.0f - wx) * wy          * vx0 * vy1;
        float w11 = wx          * wy          * vx1 * vy1;

        const float4* c00 = (const float4*)&g_field[t][j0c][i0c][lane * 4];
        const float4* c01 = (const float4*)&g_field[t][j0c][i1c][lane * 4];
        const float4* c10 = (const float4*)&g_field[t][j1c][i0c][lane * 4];
        const float4* c11 = (const float4*)&g_field[t][j1c][i1c][lane * 4];

        float4 a0 = c00[0], a1 = c00[1];
        float4 b0 = c01[0], b1 = c01[1];
        float4 e0 = c10[0], e1 = c10[1];
        float4 f0 = c11[0], f1 = c11[1];

        float4 P = blend4(a0, b0, e0, f0, w00, w01, w10, w11); // kd 4L..4L+1: (re,im,re,im)
        float4 Q = blend4(a1, b1, e1, f1, w00, w01, w10, w11); // kd 4L+2..4L+3

        // modulation weights: FREQ = 0,1,2,4,8,16,32,64 ; scale 2 for f>0
        float xt = (mc + 1.0f) * 0.5f;
        float s1, c1;
        sincospif(2.0f * xt, &s1, &c1);       // angle = 2*pi*xt (f = 1)
        float cd[8], sd[8];
        cd[0] = 1.0f; sd[0] = 0.0f;
        float cc = c1, ss = s1;
        cd[1] = 2.0f * cc; sd[1] = 2.0f * ss;
#pragma unroll
        for (int j = 2; j < 8; j++){
            float nc = cc * cc - ss * ss;
            float ns = 2.0f * cc * ss;
            cc = nc; ss = ns;
            cd[j] = 2.0f * cc; sd[j] = 2.0f * ss;
        }
        float c0s = hi ? cd[4] : cd[0], s0s = hi ? sd[4] : sd[0];
        float c1s = hi ? cd[5] : cd[1], s1s = hi ? sd[5] : sd[1];
        float c2s = hi ? cd[6] : cd[2], s2s = hi ? sd[6] : sd[2];
        float c3s = hi ? cd[7] : cd[3], s3s = hi ? sd[7] : sd[3];

        gacc += P.x * c0s - P.y * s0s
              + P.z * c1s - P.w * s1s
              + Q.x * c2s - Q.y * s2s
              + Q.z * c3s - Q.w * s3s;
    }

    // lanes (2m, 2m+1) both hold partials for k = m
    gacc += __shfl_xor_sync(0xffffffffu, gacc, 1);
    if ((lane & 1) == 0)
        out[gw * NKS + (lane >> 1)] = gacc;
}

extern "C" void kernel_launch(void* const* d_in, const int* in_sizes, int n_in,
                              void* d_out, int out_size)
{
    const float* xyz   = (const float*)d_in[0];
    const float* bound = (const float*)d_in[1];
    const float* alpha = (const float*)d_in[2];
    const float* pur   = (const float*)d_in[3];
    const float* pui   = (const float*)d_in[4];
    const float* pvr   = (const float*)d_in[5];
    const float* pvi   = (const float*)d_in[6];
    const float* pwr   = (const float*)d_in[7];
    const float* pwi   = (const float*)d_in[8];

    dim3 g1(40, 128, 3);
    pass1_kernel<<<g1, 128>>>(pur, pui, pvr, pvi, pwr, pwi, alpha);

    dim3 g2(160, 32, 3);
    pass2_kernel<<<g2, 128>>>();

    int npts = in_sizes[0] / 3;
    int nblocks = (npts * 32 + 255) / 256;
    sample_kernel<<<nblocks, 256>>>(xyz, bound, (float*)d_out, npts);
}